// round 11
// baseline (speedup 1.0000x reference)
#include <cuda_runtime.h>
#include <cstdint>

// Sliding-window (no-overlap) attention, mma.sync bf16-split, register-P,
// split accumulators to break HMMA RAW chains (ILP 6 in QK).
// B=4,S=8192,H=16,D=64,w=128,C=64. Block=(chunk,head,batch): 128 queries, 256 thr.
// d_out = out [B,S,H,64] then attn [B,S,H,384].

constexpr int Bc = 4, Sc = 8192, Hc = 16, Wn = 128, Cc = 64, NT = 256;

// smem offsets (bytes). rows have 144B stride (128B data + 16B pad).
constexpr uint32_t OFF_QH = 0;           // Q hi [128][72] bf16
constexpr uint32_t OFF_QL = 18432;
constexpr uint32_t OFF_KH = 36864;       // K hi [128 kpos][72]
constexpr uint32_t OFF_KL = 55296;
constexpr uint32_t OFF_VH = 73728;       // V hi [128 kpos][72]
constexpr uint32_t OFF_VL = 92160;
constexpr uint32_t OFF_SSUM = 110592;    // 128 floats
constexpr uint32_t SMEM_BYTES = 110592 + 512;

__device__ __forceinline__ uint32_t su32(const void* p) {
    uint32_t a;
    asm("{ .reg .u64 t; cvta.to.shared.u64 t, %1; cvt.u32.u64 %0, t; }" : "=r"(a) : "l"(p));
    return a;
}
__device__ __forceinline__ void pack_split(float v0, float v1, uint32_t& hw, uint32_t& lw) {
    asm("cvt.rn.bf16x2.f32 %0, %1, %2;" : "=r"(hw) : "f"(v1), "f"(v0));
    float r0 = v0 - __uint_as_float(hw << 16);
    float r1 = v1 - __uint_as_float(hw & 0xffff0000u);
    asm("cvt.rn.bf16x2.f32 %0, %1, %2;" : "=r"(lw) : "f"(r1), "f"(r0));
}
__device__ __forceinline__ void ldsm4(uint32_t* r, uint32_t a) {
    asm volatile("ldmatrix.sync.aligned.m8n8.x4.shared.b16 {%0,%1,%2,%3}, [%4];"
        : "=r"(r[0]), "=r"(r[1]), "=r"(r[2]), "=r"(r[3]) : "r"(a));
}
__device__ __forceinline__ void ldsm4t(uint32_t* r, uint32_t a) {
    asm volatile("ldmatrix.sync.aligned.m8n8.x4.trans.shared.b16 {%0,%1,%2,%3}, [%4];"
        : "=r"(r[0]), "=r"(r[1]), "=r"(r[2]), "=r"(r[3]) : "r"(a));
}
__device__ __forceinline__ void mma_bf16(float* d, const uint32_t* a, const uint32_t* b) {
    asm volatile("mma.sync.aligned.m16n8k16.row.col.f32.bf16.bf16.f32 "
        "{%0,%1,%2,%3}, {%4,%5,%6,%7}, {%8,%9}, {%0,%1,%2,%3};"
        : "+f"(d[0]), "+f"(d[1]), "+f"(d[2]), "+f"(d[3])
        : "r"(a[0]), "r"(a[1]), "r"(a[2]), "r"(a[3]), "r"(b[0]), "r"(b[1]));
}

__device__ __forceinline__ void sts_split(const float4* reg, char* smc,
                                          uint32_t oH, uint32_t oL, int tid) {
    #pragma unroll
    for (int i = 0; i < 8; i++) {
        int f = tid + i * NT, row = f >> 4, g = f & 15;
        float4 val = reg[i];
        uint32_t h0, l0, h1, l1;
        pack_split(val.x, val.y, h0, l0);
        pack_split(val.z, val.w, h1, l1);
        *(uint2*)(smc + oH + row * 144 + g * 8) = make_uint2(h0, h1);
        *(uint2*)(smc + oL + row * 144 + g * 8) = make_uint2(l0, l1);
    }
}
__device__ __forceinline__ void ldg_tile(float4* reg, const float* base, int tid) {
    #pragma unroll
    for (int i = 0; i < 8; i++) {
        int f = tid + i * NT;
        reg[i] = *(const float4*)(base + (size_t)(f >> 4) * 1024 + (f & 15) * 4);
    }
}

__global__ void __launch_bounds__(NT, 1)
swa_mma_kernel(const float* __restrict__ q, const float* __restrict__ k,
               const float* __restrict__ v, float* __restrict__ out,
               float* __restrict__ attn)
{
    extern __shared__ char smc[];
    const uint32_t sb = su32(smc);
    const int tid = threadIdx.x, wid = tid >> 5, lane = tid & 31;
    const int c = blockIdx.x, h = blockIdx.y, b = blockIdx.z;
    const int s0 = c * Wn;
    const int e0 = (c > 0) ? 0 : 1, e1 = (c < Cc - 1) ? 2 : 1;

    float* ssum = (float*)(smc + OFF_SSUM);
    if (tid < 128) ssum[tid] = 128.0f * (float)(e0 + 2 - e1);

    const size_t hb = (size_t)h * 64;
    const float* kbase = k + (size_t)(b * Sc) * 1024 + hb;
    const float* vbase = v + (size_t)(b * Sc) * 1024 + hb;

    // ---- prologue ----
    float4 kreg[8], vreg[8];
    ldg_tile(kreg, kbase + (size_t)(c - 1 + e0) * Wn * 1024, tid);
    {
        float4 qreg[8];
        ldg_tile(qreg, q + (size_t)(b * Sc + s0) * 1024 + hb, tid);
        sts_split(qreg, smc, OFF_QH, OFF_QL, tid);
    }
    ldg_tile(vreg, vbase + (size_t)(c - 1 + e0) * Wn * 1024, tid);
    sts_split(kreg, smc, OFF_KH, OFF_KL, tid);
    sts_split(vreg, smc, OFF_VH, OFF_VL, tid);
    __syncthreads();

    const int mrow = wid * 16;
    const int r0 = mrow + (lane >> 2);

    // ---- Q A-fragments, cached for all e ----
    uint32_t ah[4][4], al[4][4];
    #pragma unroll
    for (int kt = 0; kt < 4; kt++) {
        uint32_t ab = (uint32_t)(mrow + (lane & 15)) * 144u +
                      (uint32_t)(kt * 16 + (lane >> 4) * 8) * 2u;
        ldsm4(ah[kt], sb + OFF_QH + ab);
        ldsm4(al[kt], sb + OFF_QL + ab);
    }

    float o[8][4];
    #pragma unroll
    for (int i = 0; i < 8; i++) { o[i][0] = o[i][1] = o[i][2] = o[i][3] = 0.f; }

    float* aprow  = attn + ((size_t)(b * Sc + s0 + r0) * Hc + h) * 384;
    float* aprow8 = aprow + (size_t)8 * Hc * 384;

    for (int e = e0; e <= e1; e++) {
        if (e < e1) {   // prefetch next chunk into registers
            ldg_tile(kreg, kbase + (size_t)(c + e) * Wn * 1024, tid);
            ldg_tile(vreg, vbase + (size_t)(c + e) * Wn * 1024, tid);
        }
        float rs0 = 0.f, rs1 = 0.f;

        #pragma unroll
        for (int pair = 0; pair < 8; pair++) {
            // ---- QK strip: 6 independent accumulator chains (HH/HL/LH x 2 halves) ----
            float hh0[4] = {0,0,0,0}, hh1[4] = {0,0,0,0};
            float hl0[4] = {0,0,0,0}, hl1[4] = {0,0,0,0};
            float lh0[4] = {0,0,0,0}, lh1[4] = {0,0,0,0};
            const int mat = lane >> 3;
            #pragma unroll
            for (int kt = 0; kt < 4; kt++) {
                uint32_t ba = (uint32_t)(pair * 16 + (mat >> 1) * 8 + (lane & 7)) * 144u +
                              (uint32_t)(kt * 16 + (mat & 1) * 8) * 2u;
                uint32_t bh[4], bl[4];
                ldsm4(bh, sb + OFF_KH + ba);
                ldsm4(bl, sb + OFF_KL + ba);
                mma_bf16(hh0, ah[kt], bh);     mma_bf16(hh1, ah[kt], bh + 2);
                mma_bf16(hl0, ah[kt], bl);     mma_bf16(hl1, ah[kt], bl + 2);
                mma_bf16(lh0, al[kt], bh);     mma_bf16(lh1, al[kt], bh + 2);
            }

            // ---- exp, row sums, unnormalized attn write, pack P frags ----
            float e00 = __expf(hh0[0] + hl0[0] + lh0[0]);
            float e01 = __expf(hh0[1] + hl0[1] + lh0[1]);
            float e02 = __expf(hh0[2] + hl0[2] + lh0[2]);
            float e03 = __expf(hh0[3] + hl0[3] + lh0[3]);
            float e10 = __expf(hh1[0] + hl1[0] + lh1[0]);
            float e11 = __expf(hh1[1] + hl1[1] + lh1[1]);
            float e12 = __expf(hh1[2] + hl1[2] + lh1[2]);
            float e13 = __expf(hh1[3] + hl1[3] + lh1[3]);
            rs0 += e00 + e01 + e10 + e11;
            rs1 += e02 + e03 + e12 + e13;
            const int col = e * 128 + pair * 16 + (lane & 3) * 2;
            *(float2*)(aprow  + col)     = make_float2(e00, e01);
            *(float2*)(aprow  + col + 8) = make_float2(e10, e11);
            *(float2*)(aprow8 + col)     = make_float2(e02, e03);
            *(float2*)(aprow8 + col + 8) = make_float2(e12, e13);
            uint32_t ph[4], pl[4];
            pack_split(e00, e01, ph[0], pl[0]);
            pack_split(e02, e03, ph[1], pl[1]);
            pack_split(e10, e11, ph[2], pl[2]);
            pack_split(e12, e13, ph[3], pl[3]);

            // ---- PV(pair): kpos strip against V, 3 split passes, 8 chains ----
            #pragma unroll
            for (int nvp = 0; nvp < 4; nvp++) {
                uint32_t va = (uint32_t)(pair * 16 + (lane & 15)) * 144u +
                              (uint32_t)(nvp * 16 + (lane >> 4) * 8) * 2u;
                uint32_t vh[4], vl[4];
                ldsm4t(vh, sb + OFF_VH + va);
                ldsm4t(vl, sb + OFF_VL + va);
                mma_bf16(o[2 * nvp],     ph, vh);     mma_bf16(o[2 * nvp + 1], ph, vh + 2);
                mma_bf16(o[2 * nvp],     ph, vl);     mma_bf16(o[2 * nvp + 1], ph, vl + 2);
                mma_bf16(o[2 * nvp],     pl, vh);     mma_bf16(o[2 * nvp + 1], pl, vh + 2);
            }
        }

        rs0 += __shfl_xor_sync(0xffffffffu, rs0, 1);
        rs0 += __shfl_xor_sync(0xffffffffu, rs0, 2);
        rs1 += __shfl_xor_sync(0xffffffffu, rs1, 1);
        rs1 += __shfl_xor_sync(0xffffffffu, rs1, 2);
        if ((lane & 3) == 0) {
            atomicAdd(&ssum[r0], rs0);
            atomicAdd(&ssum[r0 + 8], rs1);
        }
        __syncthreads();   // K/V buffers free; (last e: sums complete)
        if (e < e1) {
            sts_split(kreg, smc, OFF_KH, OFF_KL, tid);
            sts_split(vreg, smc, OFF_VH, OFF_VL, tid);
        }
        __syncthreads();   // buffers valid / ssum visible
    }

    // ---- out = O * inv ----
    {
        const float i0 = 1.0f / ssum[r0], i8 = 1.0f / ssum[r0 + 8];
        float* ob  = out + ((size_t)(b * Sc + s0 + r0) * Hc + h) * 64;
        float* ob8 = ob + (size_t)8 * Hc * 64;
        #pragma unroll
        for (int nt = 0; nt < 8; nt++) {
            const int dim = nt * 8 + (lane & 3) * 2;
            *(float2*)(ob  + dim) = make_float2(o[nt][0] * i0, o[nt][1] * i0);
            *(float2*)(ob8 + dim) = make_float2(o[nt][2] * i8, o[nt][3] * i8);
        }
    }

    // ---- attn normalize pass (block-local, L2-hot) ----
    {
        const int row = tid >> 1, half = tid & 1;
        const float inv = 1.0f / ssum[row];
        float* ar = attn + ((size_t)(b * Sc + s0 + row) * Hc + h) * 384;
        #pragma unroll 4
        for (int i = 0; i < 48; i++) {
            const int col = half * 192 + i * 4;
            const int e = col >> 7;
            float4 oval;
            if (e < e0 || e > e1) {
                oval = make_float4(inv, inv, inv, inv);
            } else {
                oval = *(const float4*)(ar + col);
                oval.x *= inv; oval.y *= inv; oval.z *= inv; oval.w *= inv;
            }
            *(float4*)(ar + col) = oval;
        }
    }
}

extern "C" void kernel_launch(void* const* d_in, const int* in_sizes, int n_in,
                              void* d_out, int out_size)
{
    const float* q = (const float*)d_in[0];
    const float* k = (const float*)d_in[1];
    const float* v = (const float*)d_in[2];
    float* out  = (float*)d_out;
    float* attn = out + (size_t)Bc * Sc * Hc * 64;

    cudaFuncSetAttribute(swa_mma_kernel,
                         cudaFuncAttributeMaxDynamicSharedMemorySize, SMEM_BYTES);
    dim3 grid(Cc, Hc, Bc);
    swa_mma_kernel<<<grid, NT, SMEM_BYTES>>>(q, k, v, out, attn);
}

// round 12
// speedup vs baseline: 1.1438x; 1.1438x over previous
#include <cuda_runtime.h>
#include <cstdint>

// Sliding-window (no-overlap) attention, mma.sync bf16-split, register-P,
// 2 CTAs/SM occupancy build: Q-buffer reused for V, no reg prefetch, 128-reg cap.
// B=4,S=8192,H=16,D=64,w=128,C=64. Block=(chunk,head,batch): 128 queries, 256 thr.
// d_out = out [B,S,H,64] then attn [B,S,H,384].

constexpr int Bc = 4, Sc = 8192, Hc = 16, Wn = 128, Cc = 64, NT = 256;

// smem offsets (bytes). rows: 144B stride (128B data + 16B pad).
constexpr uint32_t OFF_AH = 0;           // Q hi, then V hi [128][72] bf16
constexpr uint32_t OFF_AL = 18432;       // Q lo, then V lo
constexpr uint32_t OFF_KH = 36864;       // K hi [128 kpos][72]
constexpr uint32_t OFF_KL = 55296;       // K lo
constexpr uint32_t OFF_SSUM = 73728;     // 128 floats
constexpr uint32_t SMEM_BYTES = 73728 + 512;   // 74240 -> 2 CTAs/SM

__device__ __forceinline__ uint32_t su32(const void* p) {
    uint32_t a;
    asm("{ .reg .u64 t; cvta.to.shared.u64 t, %1; cvt.u32.u64 %0, t; }" : "=r"(a) : "l"(p));
    return a;
}
__device__ __forceinline__ void pack_split(float v0, float v1, uint32_t& hw, uint32_t& lw) {
    asm("cvt.rn.bf16x2.f32 %0, %1, %2;" : "=r"(hw) : "f"(v1), "f"(v0));
    float r0 = v0 - __uint_as_float(hw << 16);
    float r1 = v1 - __uint_as_float(hw & 0xffff0000u);
    asm("cvt.rn.bf16x2.f32 %0, %1, %2;" : "=r"(lw) : "f"(r1), "f"(r0));
}
__device__ __forceinline__ void ldsm4(uint32_t* r, uint32_t a) {
    asm volatile("ldmatrix.sync.aligned.m8n8.x4.shared.b16 {%0,%1,%2,%3}, [%4];"
        : "=r"(r[0]), "=r"(r[1]), "=r"(r[2]), "=r"(r[3]) : "r"(a));
}
__device__ __forceinline__ void ldsm4t(uint32_t* r, uint32_t a) {
    asm volatile("ldmatrix.sync.aligned.m8n8.x4.trans.shared.b16 {%0,%1,%2,%3}, [%4];"
        : "=r"(r[0]), "=r"(r[1]), "=r"(r[2]), "=r"(r[3]) : "r"(a));
}
__device__ __forceinline__ void mma_bf16(float* d, const uint32_t* a, const uint32_t* b) {
    asm volatile("mma.sync.aligned.m16n8k16.row.col.f32.bf16.bf16.f32 "
        "{%0,%1,%2,%3}, {%4,%5,%6,%7}, {%8,%9}, {%0,%1,%2,%3};"
        : "+f"(d[0]), "+f"(d[1]), "+f"(d[2]), "+f"(d[3])
        : "r"(a[0]), "r"(a[1]), "r"(a[2]), "r"(a[3]), "r"(b[0]), "r"(b[1]));
}

// fused LDG (fp32 128x64 tile) -> split-bf16 -> STS, transient 16-reg staging
__device__ __forceinline__ void ldcvt(const float* gb, char* smc,
                                      uint32_t oH, uint32_t oL, int tid) {
    #pragma unroll
    for (int i = 0; i < 2; i++) {
        float4 t[4];
        #pragma unroll
        for (int j = 0; j < 4; j++) {
            int f = tid + (i * 4 + j) * NT;
            t[j] = *(const float4*)(gb + (size_t)(f >> 4) * 1024 + (f & 15) * 4);
        }
        #pragma unroll
        for (int j = 0; j < 4; j++) {
            int f = tid + (i * 4 + j) * NT, row = f >> 4, g = f & 15;
            uint32_t h0, l0, h1, l1;
            pack_split(t[j].x, t[j].y, h0, l0);
            pack_split(t[j].z, t[j].w, h1, l1);
            *(uint2*)(smc + oH + row * 144 + g * 8) = make_uint2(h0, h1);
            *(uint2*)(smc + oL + row * 144 + g * 8) = make_uint2(l0, l1);
        }
    }
}

__global__ void __launch_bounds__(NT, 2)
swa_mma_kernel(const float* __restrict__ q, const float* __restrict__ k,
               const float* __restrict__ v, float* __restrict__ out,
               float* __restrict__ attn)
{
    extern __shared__ char smc[];
    const uint32_t sb = su32(smc);
    const int tid = threadIdx.x, wid = tid >> 5, lane = tid & 31;
    const int c = blockIdx.x, h = blockIdx.y, b = blockIdx.z;
    const int s0 = c * Wn;
    const int e0 = (c > 0) ? 0 : 1, e1 = (c < Cc - 1) ? 2 : 1;

    float* ssum = (float*)(smc + OFF_SSUM);
    if (tid < 128) ssum[tid] = 128.0f * (float)(e0 + 2 - e1);

    const size_t hb = (size_t)h * 64;
    const float* kbase = k + (size_t)(b * Sc) * 1024 + hb;
    const float* vbase = v + (size_t)(b * Sc) * 1024 + hb;

    // ---- prologue: Q -> bufA, fragments -> regs, then bufA freed for V ----
    ldcvt(q + (size_t)(b * Sc + s0) * 1024 + hb, smc, OFF_AH, OFF_AL, tid);
    __syncthreads();

    const int mrow = wid * 16;
    const int r0 = mrow + (lane >> 2);

    uint32_t ah[4][4], al[4][4];
    #pragma unroll
    for (int kt = 0; kt < 4; kt++) {
        uint32_t ab = (uint32_t)(mrow + (lane & 15)) * 144u +
                      (uint32_t)(kt * 16 + (lane >> 4) * 8) * 2u;
        ldsm4(ah[kt], sb + OFF_AH + ab);
        ldsm4(al[kt], sb + OFF_AL + ab);
    }
    __syncthreads();   // all warps done reading Q; bufA now V staging

    float o[8][4];
    #pragma unroll
    for (int i = 0; i < 8; i++) { o[i][0] = o[i][1] = o[i][2] = o[i][3] = 0.f; }

    float* aprow  = attn + ((size_t)(b * Sc + s0 + r0) * Hc + h) * 384;
    float* aprow8 = aprow + (size_t)8 * Hc * 384;

    for (int e = e0; e <= e1; e++) {
        // K(e) -> bufK, V(e) -> bufA (L2-hot: shared across 16 heads)
        ldcvt(kbase + (size_t)(c - 1 + e) * Wn * 1024, smc, OFF_KH, OFF_KL, tid);
        ldcvt(vbase + (size_t)(c - 1 + e) * Wn * 1024, smc, OFF_AH, OFF_AL, tid);
        __syncthreads();   // tiles visible

        float rs0 = 0.f, rs1 = 0.f;
        #pragma unroll
        for (int pair = 0; pair < 8; pair++) {
            // ---- QK strip (cols pair*16..+15), 3 split passes ----
            float sc0[4] = {0.f, 0.f, 0.f, 0.f};
            float sc1[4] = {0.f, 0.f, 0.f, 0.f};
            const int mat = lane >> 3;
            #pragma unroll
            for (int kt = 0; kt < 4; kt++) {
                uint32_t ba = (uint32_t)(pair * 16 + (mat >> 1) * 8 + (lane & 7)) * 144u +
                              (uint32_t)(kt * 16 + (mat & 1) * 8) * 2u;
                uint32_t bh[4], bl[4];
                ldsm4(bh, sb + OFF_KH + ba);
                ldsm4(bl, sb + OFF_KL + ba);
                mma_bf16(sc0, ah[kt], bh);     mma_bf16(sc1, ah[kt], bh + 2);
                mma_bf16(sc0, ah[kt], bl);     mma_bf16(sc1, ah[kt], bl + 2);
                mma_bf16(sc0, al[kt], bh);     mma_bf16(sc1, al[kt], bh + 2);
            }

            // ---- exp, row sums, unnormalized attn write, pack P frags ----
            float e00 = __expf(sc0[0]), e01 = __expf(sc0[1]);
            float e02 = __expf(sc0[2]), e03 = __expf(sc0[3]);
            float e10 = __expf(sc1[0]), e11 = __expf(sc1[1]);
            float e12 = __expf(sc1[2]), e13 = __expf(sc1[3]);
            rs0 += e00 + e01 + e10 + e11;
            rs1 += e02 + e03 + e12 + e13;
            const int col = e * 128 + pair * 16 + (lane & 3) * 2;
            *(float2*)(aprow  + col)     = make_float2(e00, e01);
            *(float2*)(aprow  + col + 8) = make_float2(e10, e11);
            *(float2*)(aprow8 + col)     = make_float2(e02, e03);
            *(float2*)(aprow8 + col + 8) = make_float2(e12, e13);
            uint32_t ph[4], pl[4];
            pack_split(e00, e01, ph[0], pl[0]);
            pack_split(e02, e03, ph[1], pl[1]);
            pack_split(e10, e11, ph[2], pl[2]);
            pack_split(e12, e13, ph[3], pl[3]);

            // ---- PV(pair): kpos strip against V (bufA), 3 split passes ----
            #pragma unroll
            for (int nvp = 0; nvp < 4; nvp++) {
                uint32_t va = (uint32_t)(pair * 16 + (lane & 15)) * 144u +
                              (uint32_t)(nvp * 16 + (lane >> 4) * 8) * 2u;
                uint32_t vh[4], vl[4];
                ldsm4t(vh, sb + OFF_AH + va);
                ldsm4t(vl, sb + OFF_AL + va);
                mma_bf16(o[2 * nvp],     ph, vh);     mma_bf16(o[2 * nvp + 1], ph, vh + 2);
                mma_bf16(o[2 * nvp],     ph, vl);     mma_bf16(o[2 * nvp + 1], ph, vl + 2);
                mma_bf16(o[2 * nvp],     pl, vh);     mma_bf16(o[2 * nvp + 1], pl, vh + 2);
            }
        }

        rs0 += __shfl_xor_sync(0xffffffffu, rs0, 1);
        rs0 += __shfl_xor_sync(0xffffffffu, rs0, 2);
        rs1 += __shfl_xor_sync(0xffffffffu, rs1, 1);
        rs1 += __shfl_xor_sync(0xffffffffu, rs1, 2);
        if ((lane & 3) == 0) {
            atomicAdd(&ssum[r0], rs0);
            atomicAdd(&ssum[r0 + 8], rs1);
        }
        __syncthreads();   // K/V reads done; (after last e: ssum complete+visible)
    }

    // ---- out = O * inv ----
    {
        const float i0 = 1.0f / ssum[r0], i8 = 1.0f / ssum[r0 + 8];
        float* ob  = out + ((size_t)(b * Sc + s0 + r0) * Hc + h) * 64;
        float* ob8 = ob + (size_t)8 * Hc * 64;
        #pragma unroll
        for (int nt = 0; nt < 8; nt++) {
            const int dim = nt * 8 + (lane & 3) * 2;
            *(float2*)(ob  + dim) = make_float2(o[nt][0] * i0, o[nt][1] * i0);
            *(float2*)(ob8 + dim) = make_float2(o[nt][2] * i8, o[nt][3] * i8);
        }
    }

    // ---- attn normalize pass (block-local, L2-hot) ----
    {
        const int row = tid >> 1, half = tid & 1;
        const float inv = 1.0f / ssum[row];
        float* ar = attn + ((size_t)(b * Sc + s0 + row) * Hc + h) * 384;
        #pragma unroll 4
        for (int i = 0; i < 48; i++) {
            const int col = half * 192 + i * 4;
            const int e = col >> 7;
            float4 oval;
            if (e < e0 || e > e1) {
                oval = make_float4(inv, inv, inv, inv);
            } else {
                oval = *(const float4*)(ar + col);
                oval.x *= inv; oval.y *= inv; oval.z *= inv; oval.w *= inv;
            }
            *(float4*)(ar + col) = oval;
        }
    }
}

extern "C" void kernel_launch(void* const* d_in, const int* in_sizes, int n_in,
                              void* d_out, int out_size)
{
    const float* q = (const float*)d_in[0];
    const float* k = (const float*)d_in[1];
    const float* v = (const float*)d_in[2];
    float* out  = (float*)d_out;
    float* attn = out + (size_t)Bc * Sc * Hc * 64;

    cudaFuncSetAttribute(swa_mma_kernel,
                         cudaFuncAttributeMaxDynamicSharedMemorySize, SMEM_BYTES);
    dim3 grid(Cc, Hc, Bc);
    swa_mma_kernel<<<grid, NT, SMEM_BYTES>>>(q, k, v, out, attn);
}

// round 13
// speedup vs baseline: 1.8449x; 1.6129x over previous
#include <cuda_runtime.h>
#include <cstdint>

// Sliding-window (no-overlap) attention, mma.sync bf16-split, register-P,
// 2 CTAs/SM; coalesced row-per-warp attn normalize pass.
// B=4,S=8192,H=16,D=64,w=128,C=64. Block=(chunk,head,batch): 128 queries, 256 thr.
// d_out = out [B,S,H,64] then attn [B,S,H,384].

constexpr int Bc = 4, Sc = 8192, Hc = 16, Wn = 128, Cc = 64, NT = 256;

// smem offsets (bytes). rows: 144B stride (128B data + 16B pad).
constexpr uint32_t OFF_AH = 0;           // Q hi, then V hi [128][72] bf16
constexpr uint32_t OFF_AL = 18432;       // Q lo, then V lo
constexpr uint32_t OFF_KH = 36864;       // K hi [128 kpos][72]
constexpr uint32_t OFF_KL = 55296;       // K lo
constexpr uint32_t OFF_SSUM = 73728;     // 128 floats
constexpr uint32_t SMEM_BYTES = 73728 + 512;   // 74240 -> 2 CTAs/SM

__device__ __forceinline__ uint32_t su32(const void* p) {
    uint32_t a;
    asm("{ .reg .u64 t; cvta.to.shared.u64 t, %1; cvt.u32.u64 %0, t; }" : "=r"(a) : "l"(p));
    return a;
}
__device__ __forceinline__ void pack_split(float v0, float v1, uint32_t& hw, uint32_t& lw) {
    asm("cvt.rn.bf16x2.f32 %0, %1, %2;" : "=r"(hw) : "f"(v1), "f"(v0));
    float r0 = v0 - __uint_as_float(hw << 16);
    float r1 = v1 - __uint_as_float(hw & 0xffff0000u);
    asm("cvt.rn.bf16x2.f32 %0, %1, %2;" : "=r"(lw) : "f"(r1), "f"(r0));
}
__device__ __forceinline__ void ldsm4(uint32_t* r, uint32_t a) {
    asm volatile("ldmatrix.sync.aligned.m8n8.x4.shared.b16 {%0,%1,%2,%3}, [%4];"
        : "=r"(r[0]), "=r"(r[1]), "=r"(r[2]), "=r"(r[3]) : "r"(a));
}
__device__ __forceinline__ void ldsm4t(uint32_t* r, uint32_t a) {
    asm volatile("ldmatrix.sync.aligned.m8n8.x4.trans.shared.b16 {%0,%1,%2,%3}, [%4];"
        : "=r"(r[0]), "=r"(r[1]), "=r"(r[2]), "=r"(r[3]) : "r"(a));
}
__device__ __forceinline__ void mma_bf16(float* d, const uint32_t* a, const uint32_t* b) {
    asm volatile("mma.sync.aligned.m16n8k16.row.col.f32.bf16.bf16.f32 "
        "{%0,%1,%2,%3}, {%4,%5,%6,%7}, {%8,%9}, {%0,%1,%2,%3};"
        : "+f"(d[0]), "+f"(d[1]), "+f"(d[2]), "+f"(d[3])
        : "r"(a[0]), "r"(a[1]), "r"(a[2]), "r"(a[3]), "r"(b[0]), "r"(b[1]));
}

// fused LDG (fp32 128x64 tile) -> split-bf16 -> STS, transient 16-reg staging
__device__ __forceinline__ void ldcvt(const float* gb, char* smc,
                                      uint32_t oH, uint32_t oL, int tid) {
    #pragma unroll
    for (int i = 0; i < 2; i++) {
        float4 t[4];
        #pragma unroll
        for (int j = 0; j < 4; j++) {
            int f = tid + (i * 4 + j) * NT;
            t[j] = *(const float4*)(gb + (size_t)(f >> 4) * 1024 + (f & 15) * 4);
        }
        #pragma unroll
        for (int j = 0; j < 4; j++) {
            int f = tid + (i * 4 + j) * NT, row = f >> 4, g = f & 15;
            uint32_t h0, l0, h1, l1;
            pack_split(t[j].x, t[j].y, h0, l0);
            pack_split(t[j].z, t[j].w, h1, l1);
            *(uint2*)(smc + oH + row * 144 + g * 8) = make_uint2(h0, h1);
            *(uint2*)(smc + oL + row * 144 + g * 8) = make_uint2(l0, l1);
        }
    }
}

__global__ void __launch_bounds__(NT, 2)
swa_mma_kernel(const float* __restrict__ q, const float* __restrict__ k,
               const float* __restrict__ v, float* __restrict__ out,
               float* __restrict__ attn)
{
    extern __shared__ char smc[];
    const uint32_t sb = su32(smc);
    const int tid = threadIdx.x, wid = tid >> 5, lane = tid & 31;
    const int c = blockIdx.x, h = blockIdx.y, b = blockIdx.z;
    const int s0 = c * Wn;
    const int e0 = (c > 0) ? 0 : 1, e1 = (c < Cc - 1) ? 2 : 1;

    float* ssum = (float*)(smc + OFF_SSUM);
    if (tid < 128) ssum[tid] = 128.0f * (float)(e0 + 2 - e1);

    const size_t hb = (size_t)h * 64;
    const float* kbase = k + (size_t)(b * Sc) * 1024 + hb;
    const float* vbase = v + (size_t)(b * Sc) * 1024 + hb;

    // ---- prologue: Q -> bufA, fragments -> regs, then bufA freed for V ----
    ldcvt(q + (size_t)(b * Sc + s0) * 1024 + hb, smc, OFF_AH, OFF_AL, tid);
    __syncthreads();

    const int mrow = wid * 16;
    const int r0 = mrow + (lane >> 2);

    uint32_t ah[4][4], al[4][4];
    #pragma unroll
    for (int kt = 0; kt < 4; kt++) {
        uint32_t ab = (uint32_t)(mrow + (lane & 15)) * 144u +
                      (uint32_t)(kt * 16 + (lane >> 4) * 8) * 2u;
        ldsm4(ah[kt], sb + OFF_AH + ab);
        ldsm4(al[kt], sb + OFF_AL + ab);
    }
    __syncthreads();   // all warps done reading Q; bufA now V staging

    float o[8][4];
    #pragma unroll
    for (int i = 0; i < 8; i++) { o[i][0] = o[i][1] = o[i][2] = o[i][3] = 0.f; }

    float* aprow  = attn + ((size_t)(b * Sc + s0 + r0) * Hc + h) * 384;
    float* aprow8 = aprow + (size_t)8 * Hc * 384;

    for (int e = e0; e <= e1; e++) {
        // K(e) -> bufK, V(e) -> bufA (L2-hot: shared across 16 heads)
        ldcvt(kbase + (size_t)(c - 1 + e) * Wn * 1024, smc, OFF_KH, OFF_KL, tid);
        ldcvt(vbase + (size_t)(c - 1 + e) * Wn * 1024, smc, OFF_AH, OFF_AL, tid);
        __syncthreads();   // tiles visible

        float rs0 = 0.f, rs1 = 0.f;
        #pragma unroll
        for (int pair = 0; pair < 8; pair++) {
            // ---- QK strip (cols pair*16..+15), 3 split passes ----
            float sc0[4] = {0.f, 0.f, 0.f, 0.f};
            float sc1[4] = {0.f, 0.f, 0.f, 0.f};
            const int mat = lane >> 3;
            #pragma unroll
            for (int kt = 0; kt < 4; kt++) {
                uint32_t ba = (uint32_t)(pair * 16 + (mat >> 1) * 8 + (lane & 7)) * 144u +
                              (uint32_t)(kt * 16 + (mat & 1) * 8) * 2u;
                uint32_t bh[4], bl[4];
                ldsm4(bh, sb + OFF_KH + ba);
                ldsm4(bl, sb + OFF_KL + ba);
                mma_bf16(sc0, ah[kt], bh);     mma_bf16(sc1, ah[kt], bh + 2);
                mma_bf16(sc0, ah[kt], bl);     mma_bf16(sc1, ah[kt], bl + 2);
                mma_bf16(sc0, al[kt], bh);     mma_bf16(sc1, al[kt], bh + 2);
            }

            // ---- exp, row sums, unnormalized attn write, pack P frags ----
            float e00 = __expf(sc0[0]), e01 = __expf(sc0[1]);
            float e02 = __expf(sc0[2]), e03 = __expf(sc0[3]);
            float e10 = __expf(sc1[0]), e11 = __expf(sc1[1]);
            float e12 = __expf(sc1[2]), e13 = __expf(sc1[3]);
            rs0 += e00 + e01 + e10 + e11;
            rs1 += e02 + e03 + e12 + e13;
            const int col = e * 128 + pair * 16 + (lane & 3) * 2;
            *(float2*)(aprow  + col)     = make_float2(e00, e01);
            *(float2*)(aprow  + col + 8) = make_float2(e10, e11);
            *(float2*)(aprow8 + col)     = make_float2(e02, e03);
            *(float2*)(aprow8 + col + 8) = make_float2(e12, e13);
            uint32_t ph[4], pl[4];
            pack_split(e00, e01, ph[0], pl[0]);
            pack_split(e02, e03, ph[1], pl[1]);
            pack_split(e10, e11, ph[2], pl[2]);
            pack_split(e12, e13, ph[3], pl[3]);

            // ---- PV(pair): kpos strip against V (bufA), 3 split passes ----
            #pragma unroll
            for (int nvp = 0; nvp < 4; nvp++) {
                uint32_t va = (uint32_t)(pair * 16 + (lane & 15)) * 144u +
                              (uint32_t)(nvp * 16 + (lane >> 4) * 8) * 2u;
                uint32_t vh[4], vl[4];
                ldsm4t(vh, sb + OFF_AH + va);
                ldsm4t(vl, sb + OFF_AL + va);
                mma_bf16(o[2 * nvp],     ph, vh);     mma_bf16(o[2 * nvp + 1], ph, vh + 2);
                mma_bf16(o[2 * nvp],     ph, vl);     mma_bf16(o[2 * nvp + 1], ph, vl + 2);
                mma_bf16(o[2 * nvp],     pl, vh);     mma_bf16(o[2 * nvp + 1], pl, vh + 2);
            }
        }

        rs0 += __shfl_xor_sync(0xffffffffu, rs0, 1);
        rs0 += __shfl_xor_sync(0xffffffffu, rs0, 2);
        rs1 += __shfl_xor_sync(0xffffffffu, rs1, 1);
        rs1 += __shfl_xor_sync(0xffffffffu, rs1, 2);
        if ((lane & 3) == 0) {
            atomicAdd(&ssum[r0], rs0);
            atomicAdd(&ssum[r0 + 8], rs1);
        }
        __syncthreads();   // K/V reads done; (after last e: ssum complete+visible)
    }

    // ---- out = O * inv ----
    {
        const float i0 = 1.0f / ssum[r0], i8 = 1.0f / ssum[r0 + 8];
        float* ob  = out + ((size_t)(b * Sc + s0 + r0) * Hc + h) * 64;
        float* ob8 = ob + (size_t)8 * Hc * 64;
        #pragma unroll
        for (int nt = 0; nt < 8; nt++) {
            const int dim = nt * 8 + (lane & 3) * 2;
            *(float2*)(ob  + dim) = make_float2(o[nt][0] * i0, o[nt][1] * i0);
            *(float2*)(ob8 + dim) = make_float2(o[nt][2] * i8, o[nt][3] * i8);
        }
    }

    // ---- attn normalize pass: row-per-warp, fully coalesced float4 ----
    {
        #pragma unroll 2
        for (int rr = 0; rr < 16; rr++) {
            const int row = mrow + rr;
            const float inv = 1.0f / ssum[row];
            float* ar = attn + ((size_t)(b * Sc + s0 + row) * Hc + h) * 384;
            #pragma unroll
            for (int t = 0; t < 3; t++) {
                const int col = t * 128 + lane * 4;   // t == e index
                float4 oval;
                if (t < e0 || t > e1) {
                    oval = make_float4(inv, inv, inv, inv);
                } else {
                    oval = *(const float4*)(ar + col);
                    oval.x *= inv; oval.y *= inv; oval.z *= inv; oval.w *= inv;
                }
                *(float4*)(ar + col) = oval;
            }
        }
    }
}

extern "C" void kernel_launch(void* const* d_in, const int* in_sizes, int n_in,
                              void* d_out, int out_size)
{
    const float* q = (const float*)d_in[0];
    const float* k = (const float*)d_in[1];
    const float* v = (const float*)d_in[2];
    float* out  = (float*)d_out;
    float* attn = out + (size_t)Bc * Sc * Hc * 64;

    cudaFuncSetAttribute(swa_mma_kernel,
                         cudaFuncAttributeMaxDynamicSharedMemorySize, SMEM_BYTES);
    dim3 grid(Cc, Hc, Bc);
    swa_mma_kernel<<<grid, NT, SMEM_BYTES>>>(q, k, v, out, attn);
}